// round 6
// baseline (speedup 1.0000x reference)
#include <cuda_runtime.h>
#include <cuda_bf16.h>
#include <cuda_fp16.h>
#include <math.h>
#include <stdint.h>

#define NMAX 50000
#define EMAX 800000
#define D 128

// ---------------- scratch (static device globals; no allocation) -------------
__device__ int   g_counts[NMAX];
__device__ int   g_offsets[NMAX];
__device__ int   g_cursor[NMAX];
__device__ int   g_bsums[256];
__device__ int   g_adj[EMAX];
__device__ float g_dis[NMAX];
__device__ __half g_bufG[NMAX * D];          // fp16 message buffer (gather side)
__device__ float g_bufH[NMAX * D];           // fp32 activations (GEMM input)
__device__ __nv_bfloat16 g_WtHi[3][D * D];   // W transposed [n][k], hi part
__device__ __nv_bfloat16 g_WtLo[3][D * D];   // residual lo part

// ---------------- PTX helpers (sm_80-era: mma.sync + ldmatrix) ---------------
__device__ __forceinline__ uint32_t smem_u32(const void* p) {
    uint32_t a;
    asm("{ .reg .u64 t; cvta.to.shared.u64 t, %1; cvt.u32.u64 %0, t; }" : "=r"(a) : "l"(p));
    return a;
}

__device__ __forceinline__ void ldsm_x4(uint32_t* r, uint32_t addr) {
    asm volatile("ldmatrix.sync.aligned.m8n8.x4.shared.b16 {%0,%1,%2,%3}, [%4];"
        : "=r"(r[0]), "=r"(r[1]), "=r"(r[2]), "=r"(r[3]) : "r"(addr));
}

__device__ __forceinline__ void mma_bf16(float* c, const uint32_t* a, uint32_t b0, uint32_t b1) {
    asm volatile(
        "mma.sync.aligned.m16n8k16.row.col.f32.bf16.bf16.f32 "
        "{%0,%1,%2,%3}, {%4,%5,%6,%7}, {%8,%9}, {%0,%1,%2,%3};"
        : "+f"(c[0]), "+f"(c[1]), "+f"(c[2]), "+f"(c[3])
        : "r"(a[0]), "r"(a[1]), "r"(a[2]), "r"(a[3]), "r"(b0), "r"(b1));
}

// ---------------- preprocessing ---------------------------------------------
__global__ void k_count(const int* __restrict__ dst, int e) {
    int i = blockIdx.x * blockDim.x + threadIdx.x;
    if (i < e) atomicAdd(&g_counts[dst[i]], 1);
}

__global__ void k_scan1(int n) {
    __shared__ int sh[1024];
    int i = blockIdx.x * 1024 + threadIdx.x;
    int v = (i < n) ? g_counts[i] : 0;
    if (i < n) g_dis[i] = rsqrtf((float)(v + 1));   // +1 self loop
    sh[threadIdx.x] = v;
    __syncthreads();
    for (int off = 1; off < 1024; off <<= 1) {
        int t = 0;
        if ((int)threadIdx.x >= off) t = sh[threadIdx.x - off];
        __syncthreads();
        sh[threadIdx.x] += t;
        __syncthreads();
    }
    if (i < n) g_offsets[i] = sh[threadIdx.x] - v;
    if (threadIdx.x == 1023) g_bsums[blockIdx.x] = sh[1023];
}

__global__ void k_scan2(int nb) {
    if (threadIdx.x == 0 && blockIdx.x == 0) {
        int run = 0;
        for (int b = 0; b < nb; b++) { int t = g_bsums[b]; g_bsums[b] = run; run += t; }
    }
}

__global__ void k_scan3(int n) {
    int i = blockIdx.x * blockDim.x + threadIdx.x;
    if (i < n) g_offsets[i] += g_bsums[i >> 10];
}

__global__ void k_fill(const int* __restrict__ src, const int* __restrict__ dst, int e) {
    int i = blockIdx.x * blockDim.x + threadIdx.x;
    if (i < e) {
        int d = dst[i];
        int p = atomicAdd(&g_cursor[d], 1);
        g_adj[g_offsets[d] + p] = src[i];
    }
}

// ---------------- W transpose + bf16 split (all 3 layers, one launch) --------
__global__ void k_prep_w(const float* __restrict__ W0,
                         const float* __restrict__ W1,
                         const float* __restrict__ W2) {
    int layer = blockIdx.y;
    const float* W = (layer == 0) ? W0 : (layer == 1) ? W1 : W2;
    int nn = blockIdx.x;
    int k  = threadIdx.x;
    float v = W[k * D + nn];
    __nv_bfloat16 h = __float2bfloat16_rn(v);
    __nv_bfloat16 l = __float2bfloat16_rn(v - __bfloat162float(h));
    g_WtHi[layer][nn * D + k] = h;
    g_WtLo[layer][nn * D + k] = l;
}

// ---------------- HMMA GEMM:  G(fp16) = A @ W  (unscaled) --------------------
// 128x128 block tile, 256 threads = 8 warps (4x2), warp tile 32x64.
// bf16 hi/lo split, 3 products: Ah@Wh + Ah@Wl + Al@Wh, fp32 accum.
// NOTE: no dis scaling here -> independent of graph preprocessing.
#define BK   64
#define PADK 72
#define SM_TILE (128 * PADK)              // halves per tile
#define GEMM_SMEM (4 * SM_TILE * 2)       // bytes: Ah, Al, Wh, Wl

__global__ void __launch_bounds__(256, 2) k_gemm_mma(
    const float* __restrict__ A,
    const __nv_bfloat16* __restrict__ WtHi,
    const __nv_bfloat16* __restrict__ WtLo,
    __half* __restrict__ G, int n)
{
    extern __shared__ char smem[];
    __nv_bfloat16* sAh = (__nv_bfloat16*)smem;
    __nv_bfloat16* sAl = sAh + SM_TILE;
    __nv_bfloat16* sWh = sAl + SM_TILE;
    __nv_bfloat16* sWl = sWh + SM_TILE;

    int tid  = threadIdx.x;
    int lane = tid & 31;
    int w    = tid >> 5;
    int warp_m = w >> 1;
    int warp_n = w & 1;
    int m0 = warp_m * 32;
    int n0 = warp_n * 64;
    int row0 = blockIdx.x * 128;

    uint32_t aAh = smem_u32(sAh);
    uint32_t aAl = smem_u32(sAl);
    uint32_t aWh = smem_u32(sWh);
    uint32_t aWl = smem_u32(sWl);

    float acc[2][8][4];
#pragma unroll
    for (int mt = 0; mt < 2; mt++)
#pragma unroll
        for (int nt = 0; nt < 8; nt++)
#pragma unroll
            for (int q = 0; q < 4; q++) acc[mt][nt][q] = 0.f;

    int ldRow = tid >> 1;
    int ldCol = (tid & 1) * 32;

    for (int kc = 0; kc < 2; kc++) {
        bool okA = (row0 + ldRow) < n;
        const float4* Ar = (const float4*)(A + (size_t)(row0 + ldRow) * D + kc * BK + ldCol);
#pragma unroll
        for (int j = 0; j < 8; j++) {
            float4 v = okA ? Ar[j] : make_float4(0.f, 0.f, 0.f, 0.f);
            __nv_bfloat16 hx = __float2bfloat16_rn(v.x);
            __nv_bfloat16 hy = __float2bfloat16_rn(v.y);
            __nv_bfloat16 hz = __float2bfloat16_rn(v.z);
            __nv_bfloat16 hw = __float2bfloat16_rn(v.w);
            __nv_bfloat16 lx = __float2bfloat16_rn(v.x - __bfloat162float(hx));
            __nv_bfloat16 ly = __float2bfloat16_rn(v.y - __bfloat162float(hy));
            __nv_bfloat16 lz = __float2bfloat16_rn(v.z - __bfloat162float(hz));
            __nv_bfloat16 lw = __float2bfloat16_rn(v.w - __bfloat162float(hw));
            uint2 hp, lp;
            hp.x = ((uint32_t)__bfloat16_as_ushort(hy) << 16) | __bfloat16_as_ushort(hx);
            hp.y = ((uint32_t)__bfloat16_as_ushort(hw) << 16) | __bfloat16_as_ushort(hz);
            lp.x = ((uint32_t)__bfloat16_as_ushort(ly) << 16) | __bfloat16_as_ushort(lx);
            lp.y = ((uint32_t)__bfloat16_as_ushort(lw) << 16) | __bfloat16_as_ushort(lz);
            *(uint2*)(sAh + ldRow * PADK + ldCol + 4 * j) = hp;
            *(uint2*)(sAl + ldRow * PADK + ldCol + 4 * j) = lp;
        }
        const uint2* Wh = (const uint2*)(WtHi + ldRow * D + kc * BK + ldCol);
        const uint2* Wl = (const uint2*)(WtLo + ldRow * D + kc * BK + ldCol);
#pragma unroll
        for (int j = 0; j < 8; j++) {
            *(uint2*)(sWh + ldRow * PADK + ldCol + 4 * j) = Wh[j];
            *(uint2*)(sWl + ldRow * PADK + ldCol + 4 * j) = Wl[j];
        }
        __syncthreads();

#pragma unroll
        for (int ks = 0; ks < 4; ks++) {
            int acol = ks * 16 + ((lane >> 4) << 3);
            int lrow = lane & 15;
#pragma unroll
            for (int p = 0; p < 3; p++) {
                uint32_t ab = (p == 2) ? aAl : aAh;
                uint32_t bb = (p == 1) ? aWl : aWh;
                uint32_t af[2][4];
                ldsm_x4(af[0], ab + (uint32_t)(((m0      + lrow) * PADK + acol) * 2));
                ldsm_x4(af[1], ab + (uint32_t)(((m0 + 16 + lrow) * PADK + acol) * 2));
                uint32_t bf_[4][4];
#pragma unroll
                for (int bt = 0; bt < 4; bt++)
                    ldsm_x4(bf_[bt], bb + (uint32_t)(((n0 + bt * 16 + lrow) * PADK + acol) * 2));
#pragma unroll
                for (int mt = 0; mt < 2; mt++)
#pragma unroll
                    for (int bt = 0; bt < 4; bt++) {
                        mma_bf16(acc[mt][2 * bt],     af[mt], bf_[bt][0], bf_[bt][2]);
                        mma_bf16(acc[mt][2 * bt + 1], af[mt], bf_[bt][1], bf_[bt][3]);
                    }
            }
        }
        __syncthreads();
    }

    // ---- epilogue: store fp16 (no scaling) ----
#pragma unroll
    for (int mt = 0; mt < 2; mt++) {
        int r0 = row0 + m0 + mt * 16 + (lane >> 2);
        int r1 = r0 + 8;
#pragma unroll
        for (int nt = 0; nt < 8; nt++) {
            int col = n0 + nt * 8 + (lane & 3) * 2;
            if (r0 < n)
                *(__half2*)(G + (size_t)r0 * D + col) =
                    __floats2half2_rn(acc[mt][nt][0], acc[mt][nt][1]);
            if (r1 < n)
                *(__half2*)(G + (size_t)r1 * D + col) =
                    __floats2half2_rn(acc[mt][nt][2], acc[mt][nt][3]);
        }
    }
}

// ---------------- neighbor aggregation (one warp per node, fp16 gather) ------
// out[d] = dis[d] * ( sum_s dis[s]*g[s] + dis[d]*g[d] ) + b  [; relu]
__global__ void k_aggregate(const __half* __restrict__ G,
                            const float* __restrict__ bias,
                            float* __restrict__ out, int n, int applyRelu) {
    int warp = (blockIdx.x * blockDim.x + threadIdx.x) >> 5;
    if (warp >= n) return;
    int lane = threadIdx.x & 31;

    const uint2* G8 = (const uint2*)G;
    float ds = g_dis[warp];

    uint2 sr = G8[(size_t)warp * 32 + lane];     // self term (scaled by ds)
    float2 s0 = __half22float2(*(const __half2*)&sr.x);
    float2 s1 = __half22float2(*(const __half2*)&sr.y);
    float4 acc = make_float4(ds * s0.x, ds * s0.y, ds * s1.x, ds * s1.y);

    int start = g_offsets[warp];
    int cnt   = g_counts[warp];

    int e = 0;
    for (; e + 4 <= cnt; e += 4) {
        int i0 = g_adj[start + e + 0];
        int i1 = g_adj[start + e + 1];
        int i2 = g_adj[start + e + 2];
        int i3 = g_adj[start + e + 3];
        float d0 = g_dis[i0], d1 = g_dis[i1], d2 = g_dis[i2], d3 = g_dis[i3];
        uint2 r0 = G8[(size_t)i0 * 32 + lane];
        uint2 r1 = G8[(size_t)i1 * 32 + lane];
        uint2 r2 = G8[(size_t)i2 * 32 + lane];
        uint2 r3 = G8[(size_t)i3 * 32 + lane];
        float2 a, b;
        a = __half22float2(*(const __half2*)&r0.x); b = __half22float2(*(const __half2*)&r0.y);
        acc.x = fmaf(d0, a.x, acc.x); acc.y = fmaf(d0, a.y, acc.y);
        acc.z = fmaf(d0, b.x, acc.z); acc.w = fmaf(d0, b.y, acc.w);
        a = __half22float2(*(const __half2*)&r1.x); b = __half22float2(*(const __half2*)&r1.y);
        acc.x = fmaf(d1, a.x, acc.x); acc.y = fmaf(d1, a.y, acc.y);
        acc.z = fmaf(d1, b.x, acc.z); acc.w = fmaf(d1, b.y, acc.w);
        a = __half22float2(*(const __half2*)&r2.x); b = __half22float2(*(const __half2*)&r2.y);
        acc.x = fmaf(d2, a.x, acc.x); acc.y = fmaf(d2, a.y, acc.y);
        acc.z = fmaf(d2, b.x, acc.z); acc.w = fmaf(d2, b.y, acc.w);
        a = __half22float2(*(const __half2*)&r3.x); b = __half22float2(*(const __half2*)&r3.y);
        acc.x = fmaf(d3, a.x, acc.x); acc.y = fmaf(d3, a.y, acc.y);
        acc.z = fmaf(d3, b.x, acc.z); acc.w = fmaf(d3, b.y, acc.w);
    }
    for (; e < cnt; e++) {
        int s = g_adj[start + e];
        float dd = g_dis[s];
        uint2 r = G8[(size_t)s * 32 + lane];
        float2 a = __half22float2(*(const __half2*)&r.x);
        float2 b = __half22float2(*(const __half2*)&r.y);
        acc.x = fmaf(dd, a.x, acc.x); acc.y = fmaf(dd, a.y, acc.y);
        acc.z = fmaf(dd, b.x, acc.z); acc.w = fmaf(dd, b.y, acc.w);
    }

    float4 b4 = ((const float4*)bias)[lane];
    float4 o;
    o.x = fmaf(ds, acc.x, b4.x);
    o.y = fmaf(ds, acc.y, b4.y);
    o.z = fmaf(ds, acc.z, b4.z);
    o.w = fmaf(ds, acc.w, b4.w);
    if (applyRelu) {
        o.x = fmaxf(o.x, 0.f); o.y = fmaxf(o.y, 0.f);
        o.z = fmaxf(o.z, 0.f); o.w = fmaxf(o.w, 0.f);
    }
    ((float4*)out)[(size_t)warp * 32 + lane] = o;
}

// ---------------- launch -----------------------------------------------------
extern "C" void kernel_launch(void* const* d_in, const int* in_sizes, int n_in,
                              void* d_out, int out_size) {
    const float* x  = (const float*)d_in[0];
    const int*   ei = (const int*)d_in[1];
    const float* W0 = (const float*)d_in[2];
    const float* b0 = (const float*)d_in[3];
    const float* W1 = (const float*)d_in[4];
    const float* b1 = (const float*)d_in[5];
    const float* W2 = (const float*)d_in[6];
    const float* b2 = (const float*)d_in[7];

    int n = in_sizes[0] / D;
    int e = in_sizes[1] / 2;
    const int* src = ei;
    const int* dst = ei + e;

    __half* bufG = nullptr; float* bufH = nullptr;
    int* countsPtr = nullptr; int* cursorPtr = nullptr;
    __nv_bfloat16* wtHi = nullptr; __nv_bfloat16* wtLo = nullptr;
    cudaGetSymbolAddress((void**)&bufG, g_bufG);
    cudaGetSymbolAddress((void**)&bufH, g_bufH);
    cudaGetSymbolAddress((void**)&countsPtr, g_counts);
    cudaGetSymbolAddress((void**)&cursorPtr, g_cursor);
    cudaGetSymbolAddress((void**)&wtHi, g_WtHi);
    cudaGetSymbolAddress((void**)&wtLo, g_WtLo);
    float* out = (float*)d_out;

    cudaFuncSetAttribute(k_gemm_mma, cudaFuncAttributeMaxDynamicSharedMemorySize, GEMM_SMEM);

    // side stream + events for capture fork-join (created once, outside capture
    // on the harness's correctness call; reused by the captured graph)
    static cudaStream_t sPre = nullptr;
    static cudaEvent_t evFork = nullptr, evJoin = nullptr;
    if (sPre == nullptr) {
        cudaStreamCreateWithFlags(&sPre, cudaStreamNonBlocking);
        cudaEventCreateWithFlags(&evFork, cudaEventDisableTiming);
        cudaEventCreateWithFlags(&evJoin, cudaEventDisableTiming);
    }

    int gn = (n + 255) / 256;
    int ge = (e + 255) / 256;
    int nb = (n + 1023) / 1024;

    // ---- fork: graph preprocessing on side stream ----
    cudaEventRecord(evFork, 0);
    cudaStreamWaitEvent(sPre, evFork, 0);
    cudaMemsetAsync(countsPtr, 0, (size_t)n * sizeof(int), sPre);
    cudaMemsetAsync(cursorPtr, 0, (size_t)n * sizeof(int), sPre);
    k_count<<<ge, 256, 0, sPre>>>(dst, e);
    k_scan1<<<nb, 1024, 0, sPre>>>(n);
    k_scan2<<<1, 32, 0, sPre>>>(nb);
    k_scan3<<<gn, 256, 0, sPre>>>(n);
    k_fill <<<ge, 256, 0, sPre>>>(src, dst, e);
    cudaEventRecord(evJoin, sPre);

    // ---- main stream: weight prep + layer-0 GEMM (independent of preproc) ----
    {
        dim3 gw(D, 3);
        k_prep_w<<<gw, D>>>(W0, W1, W2);
    }

    int ggemm = (n + 127) / 128;
    int gagg  = (n * 32 + 255) / 256;

    k_gemm_mma <<<ggemm, 256, GEMM_SMEM>>>(x, wtHi + 0 * D * D, wtLo + 0 * D * D, bufG, n);

    // ---- join: aggregation needs CSR + dis ----
    cudaStreamWaitEvent(0, evJoin, 0);
    k_aggregate<<<gagg, 256>>>(bufG, b0, bufH, n, 1);
    k_gemm_mma <<<ggemm, 256, GEMM_SMEM>>>(bufH, wtHi + 1 * D * D, wtLo + 1 * D * D, bufG, n);
    k_aggregate<<<gagg, 256>>>(bufG, b1, bufH, n, 1);
    k_gemm_mma <<<ggemm, 256, GEMM_SMEM>>>(bufH, wtHi + 2 * D * D, wtLo + 2 * D * D, bufG, n);
    k_aggregate<<<gagg, 256>>>(bufG, b2, out, n, 0);
}